// round 14
// baseline (speedup 1.0000x reference)
#include <cuda_runtime.h>
#include <math.h>

// ---------------------------------------------------------------------------
// MultiHeadAttention: out = softmax((qWq^T+bq)(kWk^T+bk)^T / 8) (vWv^T+bv) Wo^T + bo
// B=4, H=8, S=2048, D=512, hd=64. Mask is a no-op in the reference.
// fp32 CUDA-core path, 8x8 micro-tiles.
// ---------------------------------------------------------------------------

#define NB   4
#define NH   8
#define SEQ  2048
#define DM   512
#define HD   64
#define MROWS (NB * SEQ)   // 8192

// Scratch (allocation-free rule -> __device__ globals). 4 x 16MB = 64MB.
__device__ float g_Q[NB * NH * SEQ * HD];   // [B,H,S,hd]
__device__ float g_K[NB * NH * SEQ * HD];
__device__ float g_V[NB * NH * SEQ * HD];
__device__ float g_A[NB * SEQ * DM];        // attention output, [B,S,D]

__device__ __forceinline__ float ex2(float x) {
    float r;
    asm("ex2.approx.ftz.f32 %0, %1;" : "=f"(r) : "f"(x));
    return r;
}

// ---------------------------------------------------------------------------
// NT GEMM: C[m,n] = sum_k X[m,k] * W[n,k] + bias[n]
// M=8192, N=512, K=512. Tiles: BM=128, BN=128, BK=16. 256 threads, 8x8 micro.
// Global loads for chunk k+1 are issued before computing chunk k (reg prefetch).
// MODE 0/1/2: write head-split into g_Q/g_K/g_V. MODE 3: X:=g_A, write [M,N].
// ---------------------------------------------------------------------------
template <int MODE>
__global__ __launch_bounds__(256)
void proj_kernel(const float* __restrict__ X,
                 const float* __restrict__ W,
                 const float* __restrict__ bias,
                 float* __restrict__ ext_out)
{
    constexpr int BK = 16;
    __shared__ __align__(16) float As[BK][128 + 4];
    __shared__ __align__(16) float Bs[BK][128 + 4];

    const float* Xin = (MODE == 3) ? g_A : X;

    const int tid = threadIdx.x;        // 0..255
    const int tx  = tid & 15;           // 8 cols each (BN=128)
    const int ty  = tid >> 4;           // 8 rows each (BM=128)
    const int m0  = blockIdx.y * 128;
    const int n0  = blockIdx.x * 128;

    const int lr = tid >> 2;            // 0..63
    const int lc = (tid & 3) * 4;       // 0,4,8,12

    const float* Ap0 = Xin + (size_t)(m0 + lr) * DM + lc;
    const float* Ap1 = Ap0 + (size_t)64 * DM;
    const float* Bp0 = W   + (size_t)(n0 + lr) * DM + lc;
    const float* Bp1 = Bp0 + (size_t)64 * DM;

    float acc[8][8];
#pragma unroll
    for (int i = 0; i < 8; i++)
#pragma unroll
        for (int j = 0; j < 8; j++) acc[i][j] = 0.f;

    // prefetch chunk 0
    float4 ra0 = *(const float4*)(Ap0);
    float4 ra1 = *(const float4*)(Ap1);
    float4 rb0 = *(const float4*)(Bp0);
    float4 rb1 = *(const float4*)(Bp1);

    for (int k0 = 0; k0 < DM; k0 += BK) {
        __syncthreads();
        As[lc + 0][lr]      = ra0.x; As[lc + 1][lr]      = ra0.y;
        As[lc + 2][lr]      = ra0.z; As[lc + 3][lr]      = ra0.w;
        As[lc + 0][lr + 64] = ra1.x; As[lc + 1][lr + 64] = ra1.y;
        As[lc + 2][lr + 64] = ra1.z; As[lc + 3][lr + 64] = ra1.w;
        Bs[lc + 0][lr]      = rb0.x; Bs[lc + 1][lr]      = rb0.y;
        Bs[lc + 2][lr]      = rb0.z; Bs[lc + 3][lr]      = rb0.w;
        Bs[lc + 0][lr + 64] = rb1.x; Bs[lc + 1][lr + 64] = rb1.y;
        Bs[lc + 2][lr + 64] = rb1.z; Bs[lc + 3][lr + 64] = rb1.w;
        __syncthreads();

        if (k0 + BK < DM) {             // issue next chunk's loads early
            ra0 = *(const float4*)(Ap0 + k0 + BK);
            ra1 = *(const float4*)(Ap1 + k0 + BK);
            rb0 = *(const float4*)(Bp0 + k0 + BK);
            rb1 = *(const float4*)(Bp1 + k0 + BK);
        }

#pragma unroll
        for (int kk = 0; kk < BK; kk++) {
            float4 av0 = *(const float4*)&As[kk][ty * 8];
            float4 av1 = *(const float4*)&As[kk][ty * 8 + 4];
            float4 bv0 = *(const float4*)&Bs[kk][tx * 8];
            float4 bv1 = *(const float4*)&Bs[kk][tx * 8 + 4];
            float a[8] = {av0.x, av0.y, av0.z, av0.w, av1.x, av1.y, av1.z, av1.w};
            float b[8] = {bv0.x, bv0.y, bv0.z, bv0.w, bv1.x, bv1.y, bv1.z, bv1.w};
#pragma unroll
            for (int i = 0; i < 8; i++)
#pragma unroll
                for (int j = 0; j < 8; j++)
                    acc[i][j] = fmaf(a[i], b[j], acc[i][j]);
        }
    }

    const int col = n0 + tx * 8;
    float4 bb0 = *(const float4*)&bias[col];
    float4 bb1 = *(const float4*)&bias[col + 4];
    float bb[8] = {bb0.x, bb0.y, bb0.z, bb0.w, bb1.x, bb1.y, bb1.z, bb1.w};

    float* outp;
    if (MODE == 0) outp = g_Q;
    else if (MODE == 1) outp = g_K;
    else if (MODE == 2) outp = g_V;
    else outp = ext_out;

#pragma unroll
    for (int i = 0; i < 8; i++) {
        const int m = m0 + ty * 8 + i;
        float4 v0, v1;
        v0.x = acc[i][0] + bb[0]; v0.y = acc[i][1] + bb[1];
        v0.z = acc[i][2] + bb[2]; v0.w = acc[i][3] + bb[3];
        v1.x = acc[i][4] + bb[4]; v1.y = acc[i][5] + bb[5];
        v1.z = acc[i][6] + bb[6]; v1.w = acc[i][7] + bb[7];
        if (MODE < 3) {
            const int b = m >> 11;          // / SEQ
            const int s = m & (SEQ - 1);
            const int h = col >> 6;         // / HD  (col is a multiple of 8; 8|64 so
            const int d = col & (HD - 1);   //  the 8-col group stays inside one head)
            float* p = &outp[(((size_t)(b * NH + h) * SEQ) + s) * HD + d];
            *(float4*)p       = v0;
            *(float4*)(p + 4) = v1;
        } else {
            float* p = &outp[(size_t)m * DM + col];
            *(float4*)p       = v0;
            *(float4*)(p + 4) = v1;
        }
    }
}

// ---------------------------------------------------------------------------
// Flash attention: per (b,h) x 128-query block, stream 64-key tiles.
// 128 threads, 8x8 micro-tiles. Q pre-scaled by 0.125*log2(e); softmax in
// base-2 domain via raw ex2.approx. P staged transposed in smem for PV.
// ---------------------------------------------------------------------------
__global__ __launch_bounds__(128, 2)
void flash_kernel()
{
    constexpr int BM = 128, BN = 64;
    constexpr int QS = BM + 4;   // 132
    constexpr int KS = BN + 4;   // 68
    constexpr int VS = HD + 4;   // 68
    constexpr int PS = BM + 4;   // 132
    constexpr float QSCALE = 0.125f * 1.4426950408889634f;  // /sqrt(64) * log2(e)

    extern __shared__ __align__(16) float sm[];
    float* Qs = sm;                     // [HD][QS]  transposed: Qs[d][r]
    float* Ks = Qs + HD * QS;           // [HD][KS]  transposed: Ks[d][t]
    float* Vs = Ks + HD * KS;           // [BN][VS]  natural:    Vs[t][d]
    float* Ps = Vs + BN * VS;           // [BN][PS]  transposed: Ps[t][r]

    const int tid = threadIdx.x;        // 0..127
    const int tx  = tid & 7;            // keys/dims: 8 groups of 8
    const int ty  = tid >> 3;           // rows: 16 groups of 8
    const int s0  = blockIdx.x * BM;
    const int bh  = blockIdx.y;         // b*NH + h

    const float* Qg = g_Q + (size_t)bh * SEQ * HD;
    const float* Kg = g_K + (size_t)bh * SEQ * HD;
    const float* Vg = g_V + (size_t)bh * SEQ * HD;

    const int lrow = tid >> 4;          // 0..7
    const int lcol = (tid & 15) * 4;    // 0..60

    // Load Q tile (scaled), transposed.
#pragma unroll
    for (int it = 0; it < 16; it++) {
        const int r = lrow + it * 8;    // 0..127
        float4 q = *(const float4*)&Qg[(size_t)(s0 + r) * HD + lcol];
        Qs[(lcol + 0) * QS + r] = q.x * QSCALE;
        Qs[(lcol + 1) * QS + r] = q.y * QSCALE;
        Qs[(lcol + 2) * QS + r] = q.z * QSCALE;
        Qs[(lcol + 3) * QS + r] = q.w * QSCALE;
    }

    float o[8][8];
    float mrow[8], lsum[8];
#pragma unroll
    for (int i = 0; i < 8; i++) {
        mrow[i] = -1e30f;
        lsum[i] = 0.f;
#pragma unroll
        for (int j = 0; j < 8; j++) o[i][j] = 0.f;
    }

    for (int kt = 0; kt < SEQ / BN; kt++) {
        const int t0 = kt * BN;
        __syncthreads();   // prior-iteration PV reads of Ks/Vs/Ps complete
#pragma unroll
        for (int it = 0; it < 8; it++) {
            const int r = lrow + it * 8;   // 0..63
            float4 kv = *(const float4*)&Kg[(size_t)(t0 + r) * HD + lcol];
            Ks[(lcol + 0) * KS + r] = kv.x;
            Ks[(lcol + 1) * KS + r] = kv.y;
            Ks[(lcol + 2) * KS + r] = kv.z;
            Ks[(lcol + 3) * KS + r] = kv.w;
            float4 vv = *(const float4*)&Vg[(size_t)(t0 + r) * HD + lcol];
            *(float4*)&Vs[r * VS + lcol] = vv;
        }
        __syncthreads();

        // S = Qs^T Ks : 128 rows x 64 keys, reduction over HD=64
        float s[8][8];
#pragma unroll
        for (int i = 0; i < 8; i++)
#pragma unroll
            for (int j = 0; j < 8; j++) s[i][j] = 0.f;

#pragma unroll 4
        for (int d = 0; d < HD; d++) {
            float4 av0 = *(const float4*)&Qs[d * QS + ty * 8];
            float4 av1 = *(const float4*)&Qs[d * QS + ty * 8 + 4];
            float4 bv0 = *(const float4*)&Ks[d * KS + tx * 8];
            float4 bv1 = *(const float4*)&Ks[d * KS + tx * 8 + 4];
            float a[8] = {av0.x, av0.y, av0.z, av0.w, av1.x, av1.y, av1.z, av1.w};
            float b[8] = {bv0.x, bv0.y, bv0.z, bv0.w, bv1.x, bv1.y, bv1.z, bv1.w};
#pragma unroll
            for (int i = 0; i < 8; i++)
#pragma unroll
                for (int j = 0; j < 8; j++)
                    s[i][j] = fmaf(a[i], b[j], s[i][j]);
        }

        // Online softmax (base-2). Row reduction across the 8-thread tx group.
#pragma unroll
        for (int i = 0; i < 8; i++) {
            float mx = s[i][0];
#pragma unroll
            for (int j = 1; j < 8; j++) mx = fmaxf(mx, s[i][j]);
#pragma unroll
            for (int off = 4; off > 0; off >>= 1)
                mx = fmaxf(mx, __shfl_xor_sync(0xffffffffu, mx, off, 8));
            const float mnew = fmaxf(mrow[i], mx);
            const float corr = ex2(mrow[i] - mnew);
            float ps = 0.f;
#pragma unroll
            for (int j = 0; j < 8; j++) {
                const float p = ex2(s[i][j] - mnew);
                ps += p;
                s[i][j] = p;
            }
#pragma unroll
            for (int off = 4; off > 0; off >>= 1)
                ps += __shfl_xor_sync(0xffffffffu, ps, off, 8);
            lsum[i] = lsum[i] * corr + ps;
            mrow[i] = mnew;
#pragma unroll
            for (int j = 0; j < 8; j++) o[i][j] *= corr;
        }

        // Stage P transposed: Ps[key][row], float4 over rows.
#pragma unroll
        for (int j = 0; j < 8; j++) {
            float* p = &Ps[(tx * 8 + j) * PS + ty * 8];
            *(float4*)p       = make_float4(s[0][j], s[1][j], s[2][j], s[3][j]);
            *(float4*)(p + 4) = make_float4(s[4][j], s[5][j], s[6][j], s[7][j]);
        }
        __syncthreads();

        // O += P V : 128 rows x 64 dims, reduction over 64 keys
#pragma unroll 4
        for (int t = 0; t < BN; t++) {
            float4 pv0 = *(const float4*)&Ps[t * PS + ty * 8];
            float4 pv1 = *(const float4*)&Ps[t * PS + ty * 8 + 4];
            float4 vv0 = *(const float4*)&Vs[t * VS + tx * 8];
            float4 vv1 = *(const float4*)&Vs[t * VS + tx * 8 + 4];
            float p[8] = {pv0.x, pv0.y, pv0.z, pv0.w, pv1.x, pv1.y, pv1.z, pv1.w};
            float vb[8] = {vv0.x, vv0.y, vv0.z, vv0.w, vv1.x, vv1.y, vv1.z, vv1.w};
#pragma unroll
            for (int i = 0; i < 8; i++)
#pragma unroll
                for (int j = 0; j < 8; j++)
                    o[i][j] = fmaf(p[i], vb[j], o[i][j]);
        }
    }

    // Epilogue: normalize, write to [B,S,D] (re-interleave heads).
    const int b = bh >> 3;
    const int h = bh & (NH - 1);
#pragma unroll
    for (int i = 0; i < 8; i++) {
        const float inv = 1.0f / lsum[i];
        const int srow = s0 + ty * 8 + i;
        float* p = &g_A[((size_t)(b * SEQ) + srow) * DM + h * HD + tx * 8];
        *(float4*)p       = make_float4(o[i][0] * inv, o[i][1] * inv,
                                        o[i][2] * inv, o[i][3] * inv);
        *(float4*)(p + 4) = make_float4(o[i][4] * inv, o[i][5] * inv,
                                        o[i][6] * inv, o[i][7] * inv);
    }
}

// ---------------------------------------------------------------------------
// kernel_launch: 5 launches, default stream, graph-capturable.
// Input order: q,k,v,mask,Wq,bq,Wk,bk,Wv,bv,Wo,bo
// ---------------------------------------------------------------------------
extern "C" void kernel_launch(void* const* d_in, const int* in_sizes, int n_in,
                              void* d_out, int out_size)
{
    (void)in_sizes; (void)n_in; (void)out_size;
    const float* q  = (const float*)d_in[0];
    const float* k  = (const float*)d_in[1];
    const float* v  = (const float*)d_in[2];
    // d_in[3] = mask (int32) — a no-op in the reference math
    const float* Wq = (const float*)d_in[4];
    const float* bq = (const float*)d_in[5];
    const float* Wk = (const float*)d_in[6];
    const float* bk = (const float*)d_in[7];
    const float* Wv = (const float*)d_in[8];
    const float* bv = (const float*)d_in[9];
    const float* Wo = (const float*)d_in[10];
    const float* bo = (const float*)d_in[11];
    float* out = (float*)d_out;

    const dim3 pgrid(DM / 128, MROWS / 128);   // (4, 64)

    proj_kernel<0><<<pgrid, 256>>>(q, Wq, bq, nullptr);
    proj_kernel<1><<<pgrid, 256>>>(k, Wk, bk, nullptr);
    proj_kernel<2><<<pgrid, 256>>>(v, Wv, bv, nullptr);

    const int smem_bytes = (HD * (128 + 4) + HD * (64 + 4) +
                            64 * (HD + 4) + 64 * (128 + 4)) * (int)sizeof(float); // 102400
    cudaFuncSetAttribute(flash_kernel,
                         cudaFuncAttributeMaxDynamicSharedMemorySize, smem_bytes);
    flash_kernel<<<dim3(SEQ / 128, NB * NH), 128, smem_bytes>>>();

    proj_kernel<3><<<pgrid, 256>>>(nullptr, Wo, bo, out);
}

// round 15
// speedup vs baseline: 1.0014x; 1.0014x over previous
#include <cuda_runtime.h>
#include <math.h>

// ---------------------------------------------------------------------------
// MultiHeadAttention: out = softmax((qWq^T+bq)(kWk^T+bk)^T / 8) (vWv^T+bv) Wo^T + bo
// B=4, H=8, S=2048, D=512, hd=64. Mask is a no-op in the reference.
// fp32 CUDA-core path, 8x8 micro-tiles.
// ---------------------------------------------------------------------------

#define NB   4
#define NH   8
#define SEQ  2048
#define DM   512
#define HD   64
#define MROWS (NB * SEQ)   // 8192

// Scratch (allocation-free rule -> __device__ globals). 4 x 16MB = 64MB.
__device__ float g_Q[NB * NH * SEQ * HD];   // [B,H,S,hd]
__device__ float g_K[NB * NH * SEQ * HD];
__device__ float g_V[NB * NH * SEQ * HD];
__device__ float g_A[NB * SEQ * DM];        // attention output, [B,S,D]

__device__ __forceinline__ float ex2(float x) {
    float r;
    asm("ex2.approx.ftz.f32 %0, %1;" : "=f"(r) : "f"(x));
    return r;
}

// ---------------------------------------------------------------------------
// NT GEMM: C[m,n] = sum_k X[m,k] * W[n,k] + bias[n]
// M=8192, N=512, K=512. Tiles: BM=128, BN=128, BK=16. 256 threads, 8x8 micro.
// Global loads for chunk k+1 are issued before computing chunk k (reg prefetch).
// MODE 0/1/2: write head-split into g_Q/g_K/g_V. MODE 3: X:=g_A, write [M,N].
// ---------------------------------------------------------------------------
template <int MODE>
__global__ __launch_bounds__(256)
void proj_kernel(const float* __restrict__ X,
                 const float* __restrict__ W,
                 const float* __restrict__ bias,
                 float* __restrict__ ext_out)
{
    constexpr int BK = 16;
    __shared__ __align__(16) float As[BK][128 + 4];
    __shared__ __align__(16) float Bs[BK][128 + 4];

    const float* Xin = (MODE == 3) ? g_A : X;

    const int tid = threadIdx.x;        // 0..255
    const int tx  = tid & 15;           // 8 cols each (BN=128)
    const int ty  = tid >> 4;           // 8 rows each (BM=128)
    const int m0  = blockIdx.y * 128;
    const int n0  = blockIdx.x * 128;

    const int lr = tid >> 2;            // 0..63
    const int lc = (tid & 3) * 4;       // 0,4,8,12

    const float* Ap0 = Xin + (size_t)(m0 + lr) * DM + lc;
    const float* Ap1 = Ap0 + (size_t)64 * DM;
    const float* Bp0 = W   + (size_t)(n0 + lr) * DM + lc;
    const float* Bp1 = Bp0 + (size_t)64 * DM;

    float acc[8][8];
#pragma unroll
    for (int i = 0; i < 8; i++)
#pragma unroll
        for (int j = 0; j < 8; j++) acc[i][j] = 0.f;

    // prefetch chunk 0
    float4 ra0 = *(const float4*)(Ap0);
    float4 ra1 = *(const float4*)(Ap1);
    float4 rb0 = *(const float4*)(Bp0);
    float4 rb1 = *(const float4*)(Bp1);

    for (int k0 = 0; k0 < DM; k0 += BK) {
        __syncthreads();
        As[lc + 0][lr]      = ra0.x; As[lc + 1][lr]      = ra0.y;
        As[lc + 2][lr]      = ra0.z; As[lc + 3][lr]      = ra0.w;
        As[lc + 0][lr + 64] = ra1.x; As[lc + 1][lr + 64] = ra1.y;
        As[lc + 2][lr + 64] = ra1.z; As[lc + 3][lr + 64] = ra1.w;
        Bs[lc + 0][lr]      = rb0.x; Bs[lc + 1][lr]      = rb0.y;
        Bs[lc + 2][lr]      = rb0.z; Bs[lc + 3][lr]      = rb0.w;
        Bs[lc + 0][lr + 64] = rb1.x; Bs[lc + 1][lr + 64] = rb1.y;
        Bs[lc + 2][lr + 64] = rb1.z; Bs[lc + 3][lr + 64] = rb1.w;
        __syncthreads();

        if (k0 + BK < DM) {             // issue next chunk's loads early
            ra0 = *(const float4*)(Ap0 + k0 + BK);
            ra1 = *(const float4*)(Ap1 + k0 + BK);
            rb0 = *(const float4*)(Bp0 + k0 + BK);
            rb1 = *(const float4*)(Bp1 + k0 + BK);
        }

#pragma unroll
        for (int kk = 0; kk < BK; kk++) {
            float4 av0 = *(const float4*)&As[kk][ty * 8];
            float4 av1 = *(const float4*)&As[kk][ty * 8 + 4];
            float4 bv0 = *(const float4*)&Bs[kk][tx * 8];
            float4 bv1 = *(const float4*)&Bs[kk][tx * 8 + 4];
            float a[8] = {av0.x, av0.y, av0.z, av0.w, av1.x, av1.y, av1.z, av1.w};
            float b[8] = {bv0.x, bv0.y, bv0.z, bv0.w, bv1.x, bv1.y, bv1.z, bv1.w};
#pragma unroll
            for (int i = 0; i < 8; i++)
#pragma unroll
                for (int j = 0; j < 8; j++)
                    acc[i][j] = fmaf(a[i], b[j], acc[i][j]);
        }
    }

    const int col = n0 + tx * 8;
    float4 bb0 = *(const float4*)&bias[col];
    float4 bb1 = *(const float4*)&bias[col + 4];
    float bb[8] = {bb0.x, bb0.y, bb0.z, bb0.w, bb1.x, bb1.y, bb1.z, bb1.w};

    float* outp;
    if (MODE == 0) outp = g_Q;
    else if (MODE == 1) outp = g_K;
    else if (MODE == 2) outp = g_V;
    else outp = ext_out;

#pragma unroll
    for (int i = 0; i < 8; i++) {
        const int m = m0 + ty * 8 + i;
        float4 v0, v1;
        v0.x = acc[i][0] + bb[0]; v0.y = acc[i][1] + bb[1];
        v0.z = acc[i][2] + bb[2]; v0.w = acc[i][3] + bb[3];
        v1.x = acc[i][4] + bb[4]; v1.y = acc[i][5] + bb[5];
        v1.z = acc[i][6] + bb[6]; v1.w = acc[i][7] + bb[7];
        if (MODE < 3) {
            const int b = m >> 11;          // / SEQ
            const int s = m & (SEQ - 1);
            const int h = col >> 6;         // / HD  (col is a multiple of 8; 8|64 so
            const int d = col & (HD - 1);   //  the 8-col group stays inside one head)
            float* p = &outp[(((size_t)(b * NH + h) * SEQ) + s) * HD + d];
            *(float4*)p       = v0;
            *(float4*)(p + 4) = v1;
        } else {
            float* p = &outp[(size_t)m * DM + col];
            *(float4*)p       = v0;
            *(float4*)(p + 4) = v1;
        }
    }
}

// ---------------------------------------------------------------------------
// Flash attention: per (b,h) x 128-query block, stream 64-key tiles.
// 128 threads, 8x8 micro-tiles. Q pre-scaled by 0.125*log2(e); softmax in
// base-2 domain via raw ex2.approx. P staged transposed in smem for PV.
// ---------------------------------------------------------------------------
__global__ __launch_bounds__(128, 2)
void flash_kernel()
{
    constexpr int BM = 128, BN = 64;
    constexpr int QS = BM + 4;   // 132
    constexpr int KS = BN + 4;   // 68
    constexpr int VS = HD + 4;   // 68
    constexpr int PS = BM + 4;   // 132
    constexpr float QSCALE = 0.125f * 1.4426950408889634f;  // /sqrt(64) * log2(e)

    extern __shared__ __align__(16) float sm[];
    float* Qs = sm;                     // [HD][QS]  transposed: Qs[d][r]
    float* Ks = Qs + HD * QS;           // [HD][KS]  transposed: Ks[d][t]
    float* Vs = Ks + HD * KS;           // [BN][VS]  natural:    Vs[t][d]
    float* Ps = Vs + BN * VS;           // [BN][PS]  transposed: Ps[t][r]

    const int tid = threadIdx.x;        // 0..127
    const int tx  = tid & 7;            // keys/dims: 8 groups of 8
    const int ty  = tid >> 3;           // rows: 16 groups of 8
    const int s0  = blockIdx.x * BM;
    const int bh  = blockIdx.y;         // b*NH + h

    const float* Qg = g_Q + (size_t)bh * SEQ * HD;
    const float* Kg = g_K + (size_t)bh * SEQ * HD;
    const float* Vg = g_V + (size_t)bh * SEQ * HD;

    const int lrow = tid >> 4;          // 0..7
    const int lcol = (tid & 15) * 4;    // 0..60

    // Load Q tile (scaled), transposed.
#pragma unroll
    for (int it = 0; it < 16; it++) {
        const int r = lrow + it * 8;    // 0..127
        float4 q = *(const float4*)&Qg[(size_t)(s0 + r) * HD + lcol];
        Qs[(lcol + 0) * QS + r] = q.x * QSCALE;
        Qs[(lcol + 1) * QS + r] = q.y * QSCALE;
        Qs[(lcol + 2) * QS + r] = q.z * QSCALE;
        Qs[(lcol + 3) * QS + r] = q.w * QSCALE;
    }

    float o[8][8];
    float mrow[8], lsum[8];
#pragma unroll
    for (int i = 0; i < 8; i++) {
        mrow[i] = -1e30f;
        lsum[i] = 0.f;
#pragma unroll
        for (int j = 0; j < 8; j++) o[i][j] = 0.f;
    }

    for (int kt = 0; kt < SEQ / BN; kt++) {
        const int t0 = kt * BN;
        __syncthreads();   // prior-iteration PV reads of Ks/Vs/Ps complete
#pragma unroll
        for (int it = 0; it < 8; it++) {
            const int r = lrow + it * 8;   // 0..63
            float4 kv = *(const float4*)&Kg[(size_t)(t0 + r) * HD + lcol];
            Ks[(lcol + 0) * KS + r] = kv.x;
            Ks[(lcol + 1) * KS + r] = kv.y;
            Ks[(lcol + 2) * KS + r] = kv.z;
            Ks[(lcol + 3) * KS + r] = kv.w;
            float4 vv = *(const float4*)&Vg[(size_t)(t0 + r) * HD + lcol];
            *(float4*)&Vs[r * VS + lcol] = vv;
        }
        __syncthreads();

        // S = Qs^T Ks : 128 rows x 64 keys, reduction over HD=64
        float s[8][8];
#pragma unroll
        for (int i = 0; i < 8; i++)
#pragma unroll
            for (int j = 0; j < 8; j++) s[i][j] = 0.f;

#pragma unroll 4
        for (int d = 0; d < HD; d++) {
            float4 av0 = *(const float4*)&Qs[d * QS + ty * 8];
            float4 av1 = *(const float4*)&Qs[d * QS + ty * 8 + 4];
            float4 bv0 = *(const float4*)&Ks[d * KS + tx * 8];
            float4 bv1 = *(const float4*)&Ks[d * KS + tx * 8 + 4];
            float a[8] = {av0.x, av0.y, av0.z, av0.w, av1.x, av1.y, av1.z, av1.w};
            float b[8] = {bv0.x, bv0.y, bv0.z, bv0.w, bv1.x, bv1.y, bv1.z, bv1.w};
#pragma unroll
            for (int i = 0; i < 8; i++)
#pragma unroll
                for (int j = 0; j < 8; j++)
                    s[i][j] = fmaf(a[i], b[j], s[i][j]);
        }

        // Online softmax (base-2). Row reduction across the 8-thread tx group.
#pragma unroll
        for (int i = 0; i < 8; i++) {
            float mx = s[i][0];
#pragma unroll
            for (int j = 1; j < 8; j++) mx = fmaxf(mx, s[i][j]);
#pragma unroll
            for (int off = 4; off > 0; off >>= 1)
                mx = fmaxf(mx, __shfl_xor_sync(0xffffffffu, mx, off, 8));
            const float mnew = fmaxf(mrow[i], mx);
            const float corr = ex2(mrow[i] - mnew);
            float ps = 0.f;
#pragma unroll
            for (int j = 0; j < 8; j++) {
                const float p = ex2(s[i][j] - mnew);
                ps += p;
                s[i][j] = p;
            }
#pragma unroll
            for (int off = 4; off > 0; off >>= 1)
                ps += __shfl_xor_sync(0xffffffffu, ps, off, 8);
            lsum[i] = lsum[i] * corr + ps;
            mrow[i] = mnew;
#pragma unroll
            for (int j = 0; j < 8; j++) o[i][j] *= corr;
        }

        // Stage P transposed: Ps[key][row], float4 over rows.
#pragma unroll
        for (int j = 0; j < 8; j++) {
            float* p = &Ps[(tx * 8 + j) * PS + ty * 8];
            *(float4*)p       = make_float4(s[0][j], s[1][j], s[2][j], s[3][j]);
            *(float4*)(p + 4) = make_float4(s[4][j], s[5][j], s[6][j], s[7][j]);
        }
        __syncthreads();

        // O += P V : 128 rows x 64 dims, reduction over 64 keys
#pragma unroll 4
        for (int t = 0; t < BN; t++) {
            float4 pv0 = *(const float4*)&Ps[t * PS + ty * 8];
            float4 pv1 = *(const float4*)&Ps[t * PS + ty * 8 + 4];
            float4 vv0 = *(const float4*)&Vs[t * VS + tx * 8];
            float4 vv1 = *(const float4*)&Vs[t * VS + tx * 8 + 4];
            float p[8] = {pv0.x, pv0.y, pv0.z, pv0.w, pv1.x, pv1.y, pv1.z, pv1.w};
            float vb[8] = {vv0.x, vv0.y, vv0.z, vv0.w, vv1.x, vv1.y, vv1.z, vv1.w};
#pragma unroll
            for (int i = 0; i < 8; i++)
#pragma unroll
                for (int j = 0; j < 8; j++)
                    o[i][j] = fmaf(p[i], vb[j], o[i][j]);
        }
    }

    // Epilogue: normalize, write to [B,S,D] (re-interleave heads).
    const int b = bh >> 3;
    const int h = bh & (NH - 1);
#pragma unroll
    for (int i = 0; i < 8; i++) {
        const float inv = 1.0f / lsum[i];
        const int srow = s0 + ty * 8 + i;
        float* p = &g_A[((size_t)(b * SEQ) + srow) * DM + h * HD + tx * 8];
        *(float4*)p       = make_float4(o[i][0] * inv, o[i][1] * inv,
                                        o[i][2] * inv, o[i][3] * inv);
        *(float4*)(p + 4) = make_float4(o[i][4] * inv, o[i][5] * inv,
                                        o[i][6] * inv, o[i][7] * inv);
    }
}

// ---------------------------------------------------------------------------
// kernel_launch: 5 launches, default stream, graph-capturable.
// Input order: q,k,v,mask,Wq,bq,Wk,bk,Wv,bv,Wo,bo
// ---------------------------------------------------------------------------
extern "C" void kernel_launch(void* const* d_in, const int* in_sizes, int n_in,
                              void* d_out, int out_size)
{
    (void)in_sizes; (void)n_in; (void)out_size;
    const float* q  = (const float*)d_in[0];
    const float* k  = (const float*)d_in[1];
    const float* v  = (const float*)d_in[2];
    // d_in[3] = mask (int32) — a no-op in the reference math
    const float* Wq = (const float*)d_in[4];
    const float* bq = (const float*)d_in[5];
    const float* Wk = (const float*)d_in[6];
    const float* bk = (const float*)d_in[7];
    const float* Wv = (const float*)d_in[8];
    const float* bv = (const float*)d_in[9];
    const float* Wo = (const float*)d_in[10];
    const float* bo = (const float*)d_in[11];
    float* out = (float*)d_out;

    const dim3 pgrid(DM / 128, MROWS / 128);   // (4, 64)

    proj_kernel<0><<<pgrid, 256>>>(q, Wq, bq, nullptr);
    proj_kernel<1><<<pgrid, 256>>>(k, Wk, bk, nullptr);
    proj_kernel<2><<<pgrid, 256>>>(v, Wv, bv, nullptr);

    const int smem_bytes = (HD * (128 + 4) + HD * (64 + 4) +
                            64 * (HD + 4) + 64 * (128 + 4)) * (int)sizeof(float); // 102400
    cudaFuncSetAttribute(flash_kernel,
                         cudaFuncAttributeMaxDynamicSharedMemorySize, smem_bytes);
    flash_kernel<<<dim3(SEQ / 128, NB * NH), 128, smem_bytes>>>();

    proj_kernel<3><<<pgrid, 256>>>(nullptr, Wo, bo, out);
}

// round 16
// speedup vs baseline: 1.0702x; 1.0688x over previous
#include <cuda_runtime.h>
#include <math.h>

// ---------------------------------------------------------------------------
// MultiHeadAttention via packed fp32x2 (SASS FFMA2) CUDA-core path.
// out = softmax((qWq^T+bq)(kWk^T+bk)^T / 8) (vWv^T+bv) Wo^T + bo
// B=4, H=8, S=2048, D=512, hd=64. Mask is a no-op in the reference.
// ---------------------------------------------------------------------------

#define NB   4
#define NH   8
#define SEQ  2048
#define DM   512
#define HD   64
#define MROWS (NB * SEQ)   // 8192

typedef unsigned long long u64;

__device__ float g_Q[NB * NH * SEQ * HD];   // [B,H,S,hd]
__device__ float g_K[NB * NH * SEQ * HD];
__device__ float g_V[NB * NH * SEQ * HD];
__device__ float g_A[NB * SEQ * DM];        // attention output, [B,S,D]

__device__ __forceinline__ float ex2(float x) {
    float r;
    asm("ex2.approx.ftz.f32 %0, %1;" : "=f"(r) : "f"(x));
    return r;
}
__device__ __forceinline__ u64 pk2(float lo, float hi) {
    u64 r;
    asm("mov.b64 %0, {%1, %2};" : "=l"(r) : "f"(lo), "f"(hi));
    return r;
}
__device__ __forceinline__ void upk(u64 v, float& lo, float& hi) {
    asm("mov.b64 {%0, %1}, %2;" : "=f"(lo), "=f"(hi) : "l"(v));
}
__device__ __forceinline__ u64 ffma2(u64 a, u64 b, u64 c) {
    u64 d;
    asm("fma.rn.f32x2 %0, %1, %2, %3;" : "=l"(d) : "l"(a), "l"(b), "l"(c));
    return d;
}
__device__ __forceinline__ u64 mul2(u64 a, u64 b) {
    u64 d;
    asm("mul.rn.f32x2 %0, %1, %2;" : "=l"(d) : "l"(a), "l"(b));
    return d;
}

// ---------------------------------------------------------------------------
// NT GEMM: C[m,n] = sum_k X[m,k] * W[n,k] + bias[n]
// M=8192, N=512, K=512. BM=128, BN=128, BK=16, 256 threads.
// Micro-tile 8x8 held as 4 row-pairs x 8 cols of packed f32x2.
// ---------------------------------------------------------------------------
template <int MODE>
__global__ __launch_bounds__(256)
void proj_kernel(const float* __restrict__ X,
                 const float* __restrict__ W,
                 const float* __restrict__ bias,
                 float* __restrict__ ext_out)
{
    constexpr int BK = 16;
    __shared__ __align__(16) float As[BK][128 + 4];
    __shared__ __align__(16) float Bs[BK][128 + 4];

    const float* Xin = (MODE == 3) ? g_A : X;

    const int tid = threadIdx.x;        // 0..255
    const int tx  = tid & 15;           // 8 cols each
    const int ty  = tid >> 4;           // 8 rows each (4 packed pairs)
    const int m0  = blockIdx.y * 128;
    const int n0  = blockIdx.x * 128;

    const int lr = tid >> 2;            // 0..63
    const int lc = (tid & 3) * 4;       // 0,4,8,12

    const float* Ap0 = Xin + (size_t)(m0 + lr) * DM + lc;
    const float* Ap1 = Ap0 + (size_t)64 * DM;
    const float* Bp0 = W   + (size_t)(n0 + lr) * DM + lc;
    const float* Bp1 = Bp0 + (size_t)64 * DM;

    u64 acc[4][8];                      // [row-pair][col], f32x2 over rows
#pragma unroll
    for (int i = 0; i < 4; i++)
#pragma unroll
        for (int j = 0; j < 8; j++) acc[i][j] = 0ull;

    float4 ra0 = *(const float4*)(Ap0);
    float4 ra1 = *(const float4*)(Ap1);
    float4 rb0 = *(const float4*)(Bp0);
    float4 rb1 = *(const float4*)(Bp1);

    for (int k0 = 0; k0 < DM; k0 += BK) {
        __syncthreads();
        // As/Bs transposed: [k][row/col] -> adjacent rows contiguous
        As[lc + 0][lr]      = ra0.x; As[lc + 1][lr]      = ra0.y;
        As[lc + 2][lr]      = ra0.z; As[lc + 3][lr]      = ra0.w;
        As[lc + 0][lr + 64] = ra1.x; As[lc + 1][lr + 64] = ra1.y;
        As[lc + 2][lr + 64] = ra1.z; As[lc + 3][lr + 64] = ra1.w;
        Bs[lc + 0][lr]      = rb0.x; Bs[lc + 1][lr]      = rb0.y;
        Bs[lc + 2][lr]      = rb0.z; Bs[lc + 3][lr]      = rb0.w;
        Bs[lc + 0][lr + 64] = rb1.x; Bs[lc + 1][lr + 64] = rb1.y;
        Bs[lc + 2][lr + 64] = rb1.z; Bs[lc + 3][lr + 64] = rb1.w;
        __syncthreads();

        if (k0 + BK < DM) {
            ra0 = *(const float4*)(Ap0 + k0 + BK);
            ra1 = *(const float4*)(Ap1 + k0 + BK);
            rb0 = *(const float4*)(Bp0 + k0 + BK);
            rb1 = *(const float4*)(Bp1 + k0 + BK);
        }

#pragma unroll
        for (int kk = 0; kk < BK; kk++) {
            // a: 4 packed row-pairs, loaded as 2 x LDS.128
            ulonglong2 aa0 = *(const ulonglong2*)&As[kk][ty * 8];
            ulonglong2 aa1 = *(const ulonglong2*)&As[kk][ty * 8 + 4];
            u64 ap[4] = {aa0.x, aa0.y, aa1.x, aa1.y};
            // b: 8 scalars, splatted
            float4 bv0 = *(const float4*)&Bs[kk][tx * 8];
            float4 bv1 = *(const float4*)&Bs[kk][tx * 8 + 4];
            float bs[8] = {bv0.x, bv0.y, bv0.z, bv0.w, bv1.x, bv1.y, bv1.z, bv1.w};
            u64 bp[8];
#pragma unroll
            for (int j = 0; j < 8; j++) bp[j] = pk2(bs[j], bs[j]);
#pragma unroll
            for (int i = 0; i < 4; i++)
#pragma unroll
                for (int j = 0; j < 8; j++)
                    acc[i][j] = ffma2(ap[i], bp[j], acc[i][j]);
        }
    }

    const int col = n0 + tx * 8;
    float4 bb0 = *(const float4*)&bias[col];
    float4 bb1 = *(const float4*)&bias[col + 4];
    float bb[8] = {bb0.x, bb0.y, bb0.z, bb0.w, bb1.x, bb1.y, bb1.z, bb1.w};

    float* outp;
    if (MODE == 0) outp = g_Q;
    else if (MODE == 1) outp = g_K;
    else if (MODE == 2) outp = g_V;
    else outp = ext_out;

#pragma unroll
    for (int ip = 0; ip < 4; ip++) {
        float c0[8], c1[8];
#pragma unroll
        for (int j = 0; j < 8; j++) {
            upk(acc[ip][j], c0[j], c1[j]);
            c0[j] += bb[j];
            c1[j] += bb[j];
        }
#pragma unroll
        for (int half = 0; half < 2; half++) {
            const float* c = half ? c1 : c0;
            const int m = m0 + ty * 8 + ip * 2 + half;
            float4 v0 = make_float4(c[0], c[1], c[2], c[3]);
            float4 v1 = make_float4(c[4], c[5], c[6], c[7]);
            if (MODE < 3) {
                const int b = m >> 11;
                const int s = m & (SEQ - 1);
                const int h = col >> 6;
                const int d = col & (HD - 1);
                float* p = &outp[(((size_t)(b * NH + h) * SEQ) + s) * HD + d];
                *(float4*)p       = v0;
                *(float4*)(p + 4) = v1;
            } else {
                float* p = &outp[(size_t)m * DM + col];
                *(float4*)p       = v0;
                *(float4*)(p + 4) = v1;
            }
        }
    }
}

// ---------------------------------------------------------------------------
// Flash attention, packed f32x2. 256 threads, BM=128 queries, BN=64 keys.
// Micro-tile 8 rows x 4 keys = 4 row-pairs x 4 (packed over rows).
// Softmax in base-2 (Q pre-scaled by 0.125*log2 e, raw ex2).
// ---------------------------------------------------------------------------
__global__ __launch_bounds__(256, 2)
void flash_kernel()
{
    constexpr int BM = 128, BN = 64;
    constexpr int QS = BM + 4;   // 132
    constexpr int KS = BN + 4;   // 68
    constexpr int VS = HD + 4;   // 68
    constexpr int PS = BM + 4;   // 132
    constexpr float QSCALE = 0.125f * 1.4426950408889634f;

    extern __shared__ __align__(16) float sm[];
    float* Qs = sm;                     // [HD][QS]  Qs[d][r]
    float* Ks = Qs + HD * QS;           // [HD][KS]  Ks[d][t]
    float* Vs = Ks + HD * KS;           // [BN][VS]  Vs[t][d]
    float* Ps = Vs + BN * VS;           // [BN][PS]  Ps[t][r]

    const int tid = threadIdx.x;        // 0..255
    const int tx  = tid & 15;           // 16 groups of 4 keys/dims
    const int ty  = tid >> 4;           // 16 groups of 8 rows
    const int s0  = blockIdx.x * BM;
    const int bh  = blockIdx.y;

    const float* Qg = g_Q + (size_t)bh * SEQ * HD;
    const float* Kg = g_K + (size_t)bh * SEQ * HD;
    const float* Vg = g_V + (size_t)bh * SEQ * HD;

    const int lr0 = tid >> 4;           // 0..15
    const int lc  = (tid & 15) * 4;     // 0..60

    // Q tile (scaled), transposed.
#pragma unroll
    for (int it = 0; it < 8; it++) {
        const int r = lr0 + it * 16;
        float4 q = *(const float4*)&Qg[(size_t)(s0 + r) * HD + lc];
        Qs[(lc + 0) * QS + r] = q.x * QSCALE;
        Qs[(lc + 1) * QS + r] = q.y * QSCALE;
        Qs[(lc + 2) * QS + r] = q.z * QSCALE;
        Qs[(lc + 3) * QS + r] = q.w * QSCALE;
    }

    u64 o[4][4];                        // [row-pair][dim], f32x2 over rows
    float mrow[8], lsum[8];
#pragma unroll
    for (int i = 0; i < 8; i++) { mrow[i] = -1e30f; lsum[i] = 0.f; }
#pragma unroll
    for (int i = 0; i < 4; i++)
#pragma unroll
        for (int j = 0; j < 4; j++) o[i][j] = 0ull;

    for (int kt = 0; kt < SEQ / BN; kt++) {
        const int t0 = kt * BN;
        __syncthreads();
#pragma unroll
        for (int it = 0; it < 4; it++) {
            const int r = lr0 + it * 16;   // 0..63
            float4 kv = *(const float4*)&Kg[(size_t)(t0 + r) * HD + lc];
            Ks[(lc + 0) * KS + r] = kv.x;
            Ks[(lc + 1) * KS + r] = kv.y;
            Ks[(lc + 2) * KS + r] = kv.z;
            Ks[(lc + 3) * KS + r] = kv.w;
            float4 vv = *(const float4*)&Vg[(size_t)(t0 + r) * HD + lc];
            *(float4*)&Vs[r * VS + lc] = vv;
        }
        __syncthreads();

        // S = Qs^T Ks : packed over row pairs
        u64 s_pk[4][4];
#pragma unroll
        for (int i = 0; i < 4; i++)
#pragma unroll
            for (int j = 0; j < 4; j++) s_pk[i][j] = 0ull;

#pragma unroll 4
        for (int d = 0; d < HD; d++) {
            ulonglong2 aa0 = *(const ulonglong2*)&Qs[d * QS + ty * 8];
            ulonglong2 aa1 = *(const ulonglong2*)&Qs[d * QS + ty * 8 + 4];
            u64 ap[4] = {aa0.x, aa0.y, aa1.x, aa1.y};
            float4 bv = *(const float4*)&Ks[d * KS + tx * 4];
            float bs[4] = {bv.x, bv.y, bv.z, bv.w};
            u64 bp[4];
#pragma unroll
            for (int j = 0; j < 4; j++) bp[j] = pk2(bs[j], bs[j]);
#pragma unroll
            for (int i = 0; i < 4; i++)
#pragma unroll
                for (int j = 0; j < 4; j++)
                    s_pk[i][j] = ffma2(ap[i], bp[j], s_pk[i][j]);
        }

        // Online softmax per row-pair; stage exp(P) transposed as u64 pairs.
#pragma unroll
        for (int ip = 0; ip < 4; ip++) {
            float a0[4], a1[4];
#pragma unroll
            for (int j = 0; j < 4; j++) upk(s_pk[ip][j], a0[j], a1[j]);
            const int r0 = ip * 2, r1 = ip * 2 + 1;

            float mx0 = fmaxf(fmaxf(a0[0], a0[1]), fmaxf(a0[2], a0[3]));
            float mx1 = fmaxf(fmaxf(a1[0], a1[1]), fmaxf(a1[2], a1[3]));
#pragma unroll
            for (int off = 8; off > 0; off >>= 1) {
                mx0 = fmaxf(mx0, __shfl_xor_sync(0xffffffffu, mx0, off, 16));
                mx1 = fmaxf(mx1, __shfl_xor_sync(0xffffffffu, mx1, off, 16));
            }
            const float mn0 = fmaxf(mrow[r0], mx0);
            const float mn1 = fmaxf(mrow[r1], mx1);
            const float cr0 = ex2(mrow[r0] - mn0);
            const float cr1 = ex2(mrow[r1] - mn1);
            float ps0 = 0.f, ps1 = 0.f;
            float e0[4], e1[4];
#pragma unroll
            for (int j = 0; j < 4; j++) {
                e0[j] = ex2(a0[j] - mn0); ps0 += e0[j];
                e1[j] = ex2(a1[j] - mn1); ps1 += e1[j];
            }
#pragma unroll
            for (int off = 8; off > 0; off >>= 1) {
                ps0 += __shfl_xor_sync(0xffffffffu, ps0, off, 16);
                ps1 += __shfl_xor_sync(0xffffffffu, ps1, off, 16);
            }
            lsum[r0] = lsum[r0] * cr0 + ps0;
            lsum[r1] = lsum[r1] * cr1 + ps1;
            mrow[r0] = mn0;
            mrow[r1] = mn1;
            const u64 crp = pk2(cr0, cr1);
#pragma unroll
            for (int j = 0; j < 4; j++) {
                o[ip][j] = mul2(o[ip][j], crp);
                *(u64*)&Ps[(tx * 4 + j) * PS + ty * 8 + ip * 2] = pk2(e0[j], e1[j]);
            }
        }
        __syncthreads();

        // O += P V : packed over row pairs
#pragma unroll 4
        for (int t = 0; t < BN; t++) {
            ulonglong2 pp0 = *(const ulonglong2*)&Ps[t * PS + ty * 8];
            ulonglong2 pp1 = *(const ulonglong2*)&Ps[t * PS + ty * 8 + 4];
            u64 pv[4] = {pp0.x, pp0.y, pp1.x, pp1.y};
            float4 vv = *(const float4*)&Vs[t * VS + tx * 4];
            float vs[4] = {vv.x, vv.y, vv.z, vv.w};
            u64 vp[4];
#pragma unroll
            for (int j = 0; j < 4; j++) vp[j] = pk2(vs[j], vs[j]);
#pragma unroll
            for (int i = 0; i < 4; i++)
#pragma unroll
                for (int j = 0; j < 4; j++)
                    o[i][j] = ffma2(pv[i], vp[j], o[i][j]);
        }
    }

    // Epilogue: normalize, write [B,S,D].
    const int b = bh >> 3;
    const int h = bh & (NH - 1);
#pragma unroll
    for (int ip = 0; ip < 4; ip++) {
        float c0[4], c1[4];
#pragma unroll
        for (int j = 0; j < 4; j++) upk(o[ip][j], c0[j], c1[j]);
        const float inv0 = 1.0f / lsum[ip * 2];
        const float inv1 = 1.0f / lsum[ip * 2 + 1];
        const int r0 = s0 + ty * 8 + ip * 2;
        float* p0 = &g_A[((size_t)(b * SEQ) + r0) * DM + h * HD + tx * 4];
        float* p1 = p0 + DM;
        *(float4*)p0 = make_float4(c0[0] * inv0, c0[1] * inv0, c0[2] * inv0, c0[3] * inv0);
        *(float4*)p1 = make_float4(c1[0] * inv1, c1[1] * inv1, c1[2] * inv1, c1[3] * inv1);
    }
}

// ---------------------------------------------------------------------------
// kernel_launch: 5 launches, default stream, graph-capturable.
// Input order: q,k,v,mask,Wq,bq,Wk,bk,Wv,bv,Wo,bo
// ---------------------------------------------------------------------------
extern "C" void kernel_launch(void* const* d_in, const int* in_sizes, int n_in,
                              void* d_out, int out_size)
{
    (void)in_sizes; (void)n_in; (void)out_size;
    const float* q  = (const float*)d_in[0];
    const float* k  = (const float*)d_in[1];
    const float* v  = (const float*)d_in[2];
    // d_in[3] = mask — no-op in the reference math
    const float* Wq = (const float*)d_in[4];
    const float* bq = (const float*)d_in[5];
    const float* Wk = (const float*)d_in[6];
    const float* bk = (const float*)d_in[7];
    const float* Wv = (const float*)d_in[8];
    const float* bv = (const float*)d_in[9];
    const float* Wo = (const float*)d_in[10];
    const float* bo = (const float*)d_in[11];
    float* out = (float*)d_out;

    const dim3 pgrid(DM / 128, MROWS / 128);   // (4, 64)

    proj_kernel<0><<<pgrid, 256>>>(q, Wq, bq, nullptr);
    proj_kernel<1><<<pgrid, 256>>>(k, Wk, bk, nullptr);
    proj_kernel<2><<<pgrid, 256>>>(v, Wv, bv, nullptr);

    const int smem_bytes = (HD * (128 + 4) + HD * (64 + 4) +
                            64 * (HD + 4) + 64 * (128 + 4)) * (int)sizeof(float); // 102400
    cudaFuncSetAttribute(flash_kernel,
                         cudaFuncAttributeMaxDynamicSharedMemorySize, smem_bytes);
    flash_kernel<<<dim3(SEQ / 128, NB * NH), 256, smem_bytes>>>();

    proj_kernel<3><<<pgrid, 256>>>(nullptr, Wo, bo, out);
}